// round 1
// baseline (speedup 1.0000x reference)
#include <cuda_runtime.h>
#include <cstdint>

#define B_TOT 4096
#define T_TOT 512
#define F_TOT 25
#define NGRP  (B_TOT / 32)   // 128 batch groups

// Scratch: gate pre-activations, layout [bg][t][lane][8] floats (64 MB).
__device__ float g_gates[(size_t)B_TOT * T_TOT * 8];

__device__ __forceinline__ float tanha(float v) {
    float y;
    asm("tanh.approx.f32 %0, %1;" : "=f"(y) : "f"(v));
    return y;
}

// ---------------------------------------------------------------------------
// K1: gates_pre = W_ih · x + b   (i,f,o rows pre-scaled by 0.5 for tanh trick)
// Block = 256 threads: 32 batches (lanes) x 8 timesteps (warps).
// ---------------------------------------------------------------------------
__global__ __launch_bounds__(256) void gates_kernel(
    const float* __restrict__ x,
    const float* __restrict__ Wih1, const float* __restrict__ b1,
    const float* __restrict__ Wih2, const float* __restrict__ b2)
{
    __shared__ float sx[32][201];   // 32 batch rows x 200 floats, pad->stride 201 (bank 9, conflict-free)
    __shared__ float sw[8][16];     // sw[g][f]: g 0..3 = LSTM1 (12 in), 4..7 = LSTM2 (13 in)
    __shared__ float sb[8];

    const int tid = threadIdx.x;

    // Load + fold weights (0.5x on i,f,o rows; g row raw)
    if (tid < 48) {
        int g = tid / 12, f = tid % 12;
        float v = Wih1[tid];
        if (g != 2) v *= 0.5f;
        sw[g][f] = v;
    } else if (tid < 100) {
        int j = tid - 48;
        int g = j / 13, f = j % 13;
        float v = Wih2[j];
        if (g != 2) v *= 0.5f;
        sw[4 + g][f] = v;
    } else if (tid < 108) {
        int j = tid - 100;
        float v = (j < 4) ? b1[j] : b2[j - 4];
        if ((j & 3) != 2) v *= 0.5f;
        sb[j] = v;
    }

    const int bg = blockIdx.x >> 6;          // 0..127
    const int t0 = (blockIdx.x & 63) << 3;   // 0,8,...,504

    // Cooperative coalesced stage of x[bg*32 .. +32][t0 .. t0+8][0..25)
    #pragma unroll
    for (int i = 0; i < 25; i++) {
        int idx = i * 256 + tid;             // 0..6399
        int bl = idx / 200;
        int f  = idx % 200;
        sx[bl][f] = x[((size_t)(bg * 32 + bl) * T_TOT + t0) * F_TOT + f];
    }
    __syncthreads();

    const int bl = tid & 31;   // lane = batch-in-group
    const int tl = tid >> 5;   // warp  = timestep-in-tile

    float xv[25];
    const float* xr = &sx[bl][tl * F_TOT];
    #pragma unroll
    for (int f = 0; f < 25; f++) xv[f] = xr[f];

    float acc[8];
    #pragma unroll
    for (int g = 0; g < 4; g++) {
        float a = sb[g];
        #pragma unroll
        for (int f = 0; f < 12; f++) a = fmaf(sw[g][f], xv[f], a);
        acc[g] = a;
    }
    #pragma unroll
    for (int g = 0; g < 4; g++) {
        float a = sb[4 + g];
        #pragma unroll
        for (int f = 0; f < 13; f++) a = fmaf(sw[4 + g][f], xv[12 + f], a);
        acc[4 + g] = a;
    }

    // Tiled store: [bg][t][lane][8]; per-instr the warp writes contiguous 512B.
    float4* gp = (float4*)(g_gates + ((size_t)(bg * T_TOT + t0 + tl) * 32 + bl) * 8);
    gp[0] = make_float4(acc[0], acc[1], acc[2], acc[3]);
    gp[1] = make_float4(acc[4], acc[5], acc[6], acc[7]);
}

// ---------------------------------------------------------------------------
// K2: serial recurrence. 128 blocks x 64 threads.
// warp 0 -> LSTM1, warp 1 -> LSTM2; lane = batch within group.
// Depth-8 register-ring prefetch of gate float4s (coalesced loads).
// ---------------------------------------------------------------------------
__global__ __launch_bounds__(64) void rnn_kernel(
    const float* __restrict__ Whh1, const float* __restrict__ Whh2,
    const float* __restrict__ Wout, const float* __restrict__ bout,
    float* __restrict__ out)
{
    __shared__ float sh2[32];

    const int bg   = blockIdx.x;
    const int lane = threadIdx.x & 31;
    const int wid  = threadIdx.x >> 5;   // 0: LSTM1, 1: LSTM2

    const float* Whh = (wid == 0) ? Whh1 : Whh2;
    const float whi = Whh[0] * 0.5f;
    const float whf = Whh[1] * 0.5f;
    const float whg = Whh[2];
    const float who = Whh[3] * 0.5f;

    // lane's gate quad for this LSTM at t: stride 64 float4 per timestep
    const float4* p = (const float4*)(g_gates + ((size_t)bg * T_TOT * 32 + lane) * 8) + wid;

    const int D = 8;
    float4 buf[D];
    #pragma unroll
    for (int d = 0; d < D; d++) buf[d] = p[(size_t)d * 64];

    float h = 0.0f, c = 0.0f;

    for (int to = 0; to < T_TOT; to += D) {
        #pragma unroll
        for (int d = 0; d < D; d++) {
            float4 z = buf[d];
            int tp = to + d + D;
            if (tp < T_TOT) buf[d] = p[(size_t)tp * 64];

            // pre-activations: x/y/w already 0.5-scaled in K1
            float zi = fmaf(whi, h, z.x);
            float zf = fmaf(whf, h, z.y);
            float zg = fmaf(whg, h, z.z);
            float zo = fmaf(who, h, z.w);

            float gi = fmaf(0.5f, tanha(zi), 0.5f);   // sigmoid
            float gf = fmaf(0.5f, tanha(zf), 0.5f);
            float gg = tanha(zg);
            float go = fmaf(0.5f, tanha(zo), 0.5f);

            c = fmaf(gf, c, gi * gg);
            h = go * tanha(c);
        }
    }

    if (wid == 1) sh2[lane] = h;
    __syncthreads();
    if (wid == 0) {
        float h2 = sh2[lane];
        float y = fmaf(Wout[0], h, fmaf(Wout[1], h2, bout[0]));
        out[bg * 32 + lane] = 1.0f / (1.0f + __expf(-y));
    }
}

// ---------------------------------------------------------------------------
extern "C" void kernel_launch(void* const* d_in, const int* in_sizes, int n_in,
                              void* d_out, int out_size)
{
    const float* x    = (const float*)d_in[0];
    const float* Wih1 = (const float*)d_in[1];
    const float* Whh1 = (const float*)d_in[2];
    const float* b1   = (const float*)d_in[3];
    const float* Wih2 = (const float*)d_in[4];
    const float* Whh2 = (const float*)d_in[5];
    const float* b2   = (const float*)d_in[6];
    const float* Wout = (const float*)d_in[7];
    const float* bout = (const float*)d_in[8];

    gates_kernel<<<NGRP * (T_TOT / 8), 256>>>(x, Wih1, b1, Wih2, b2);
    rnn_kernel<<<NGRP, 64>>>(Whh1, Whh2, Wout, bout, (float*)d_out);
}

// round 2
// speedup vs baseline: 1.1712x; 1.1712x over previous
#include <cuda_runtime.h>
#include <cstdint>

#define NGRP    128          // 4096 / 32 batch groups
#define T_TOT   512
#define TILE_T  16
#define NTILE   (T_TOT / TILE_T)   // 32
#define SLOTS   4
#define PROD_T  512
#define CONS_T  64
#define NTHREADS (PROD_T + CONS_T) // 576

#define XROW        401                         // 400 floats + 1 pad (odd stride -> conflict-free)
#define RING_FLOATS (SLOTS * TILE_T * 256)      // 16384 floats = 64 KB
#define XBUF_FLOATS (2 * 32 * XROW)             // 25664 floats = 102.6 KB
#define SMEM_BYTES  ((RING_FLOATS + XBUF_FLOATS) * 4 + 64)

__device__ __forceinline__ float tanha(float v) {
    float y;
    asm("tanh.approx.f32 %0, %1;" : "=f"(y) : "f"(v));
    return y;
}

__device__ __forceinline__ uint32_t smem_u32(const void* p) {
    uint32_t a;
    asm("{ .reg .u64 t; cvta.to.shared.u64 t, %1; cvt.u32.u64 %0, t; }" : "=r"(a) : "l"(p));
    return a;
}

#define MBAR_INIT(addr, cnt) \
    asm volatile("mbarrier.init.shared.b64 [%0], %1;" :: "r"(addr), "r"(cnt) : "memory")
#define MBAR_ARRIVE(addr) \
    asm volatile("mbarrier.arrive.shared.b64 _, [%0];" :: "r"(addr) : "memory")

__device__ __forceinline__ void mbar_wait_parity(uint32_t mbar, uint32_t parity) {
    uint32_t done;
    asm volatile(
        "{\n\t.reg .pred p;\n\t"
        "mbarrier.try_wait.parity.acquire.cta.shared::cta.b64 p, [%1], %2;\n\t"
        "selp.b32 %0, 1, 0, p;\n\t}"
        : "=r"(done) : "r"(mbar), "r"(parity) : "memory");
    if (!done) {
        asm volatile(
            "{\n\t.reg .pred P1;\n\t"
            "W_%=:\n\t"
            "mbarrier.try_wait.parity.acquire.cta.shared::cta.b64 P1, [%0], %1, 0x989680;\n\t"
            "@P1 bra.uni D_%=;\n\t"
            "bra.uni W_%=;\n\t"
            "D_%=:\n\t}"
            :: "r"(mbar), "r"(parity) : "memory");
    }
}

// ---------------------------------------------------------------------------
// Fused kernel: one block per 32-batch group.
//  warps 0..15 : producers — stream x, compute gate pre-activations -> SMEM ring
//  warp 16     : consumer LSTM1 (lane = batch)
//  warp 17     : consumer LSTM2
// ---------------------------------------------------------------------------
__global__ __launch_bounds__(NTHREADS, 1) void fused_kernel(
    const float* __restrict__ x,
    const float* __restrict__ Wih1, const float* __restrict__ Whh1, const float* __restrict__ b1,
    const float* __restrict__ Wih2, const float* __restrict__ Whh2, const float* __restrict__ b2,
    const float* __restrict__ Wout, const float* __restrict__ bout,
    float* __restrict__ out)
{
    extern __shared__ float smem[];
    float* ring = smem;                       // [SLOTS][TILE_T][256]
    float* xbuf = smem + RING_FLOATS;         // [2][32][XROW]

    __shared__ float sw[8][16];
    __shared__ float sb[8];
    __shared__ float h2s[32];

    const int tid = threadIdx.x;
    const int bg  = blockIdx.x;

    const uint32_t bar_base  = smem_u32(smem) + (RING_FLOATS + XBUF_FLOATS) * 4;
    const uint32_t full_base  = bar_base;          // 4 x 8B
    const uint32_t empty_base = bar_base + 32;     // 4 x 8B

    // Fold weights: 0.5x on i,f,o rows (tanh-sigmoid identity); g row raw.
    if (tid < 48) {
        int g = tid / 12, f = tid % 12;
        float v = Wih1[tid];
        if (g != 2) v *= 0.5f;
        sw[g][f] = v;
    } else if (tid < 100) {
        int j = tid - 48;
        int g = j / 13, f = j % 13;
        float v = Wih2[j];
        if (g != 2) v *= 0.5f;
        sw[4 + g][f] = v;
    } else if (tid < 108) {
        int j = tid - 100;
        float v = (j < 4) ? b1[j] : b2[j - 4];
        if ((j & 3) != 2) v *= 0.5f;
        sb[j] = v;
    } else if (tid == 108) {
        #pragma unroll
        for (int s = 0; s < SLOTS; s++) {
            MBAR_INIT(full_base  + s * 8, PROD_T);
            MBAR_INIT(empty_base + s * 8, CONS_T);
        }
    }
    __syncthreads();

    if (tid < PROD_T) {
        // ================= PRODUCER =================
        const int bl = tid & 31;     // batch lane
        const int tl = tid >> 5;     // timestep within tile (warp id 0..15)
        const size_t xbase = (size_t)bg * (32 * T_TOT * 25);

        float r[25];   // register-staged x tile (coalesced LDG)

        // j-loop: i = j*512+tid in [0,12800): b=i/400 (batch row), f=i%400 (16t x 25f)
        #define LDG_TILE(K) do {                                            \
            size_t tb = xbase + (size_t)(K) * (TILE_T * 25);                \
            _Pragma("unroll")                                               \
            for (int j = 0; j < 25; j++) {                                  \
                int i = j * PROD_T + tid;                                   \
                int b = i / 400, f = i % 400;                               \
                r[j] = x[tb + (size_t)b * (T_TOT * 25) + f];                \
            } } while (0)

        #define STS_TILE(BUF) do {                                          \
            _Pragma("unroll")                                               \
            for (int j = 0; j < 25; j++) {                                  \
                int i = j * PROD_T + tid;                                   \
                int b = i / 400, f = i % 400;                               \
                xbuf[((BUF) * 32 + b) * XROW + f] = r[j];                   \
            } } while (0)

        LDG_TILE(0);
        STS_TILE(0);
        asm volatile("bar.sync 1, %0;" :: "n"(PROD_T) : "memory");
        LDG_TILE(1);

        for (int k = 0; k < NTILE; k++) {
            const int buf = k & 1;
            const int s   = k & (SLOTS - 1);
            const uint32_t pe = 1u ^ ((k >> 2) & 1);  // producer empty-phase (starts flipped)

            mbar_wait_parity(empty_base + s * 8, pe);

            // gates for (bl, t = k*16 + tl)
            const float* xr = &xbuf[(buf * 32 + bl) * XROW + tl * 25];
            float a0 = sb[0], a1 = sb[1], a2 = sb[2], a3 = sb[3];
            #pragma unroll
            for (int f = 0; f < 12; f++) {
                float v = xr[f];
                a0 = fmaf(sw[0][f], v, a0);
                a1 = fmaf(sw[1][f], v, a1);
                a2 = fmaf(sw[2][f], v, a2);
                a3 = fmaf(sw[3][f], v, a3);
            }
            float a4 = sb[4], a5 = sb[5], a6 = sb[6], a7 = sb[7];
            #pragma unroll
            for (int f = 0; f < 13; f++) {
                float v = xr[12 + f];
                a4 = fmaf(sw[4][f], v, a4);
                a5 = fmaf(sw[5][f], v, a5);
                a6 = fmaf(sw[6][f], v, a6);
                a7 = fmaf(sw[7][f], v, a7);
            }

            float* rb = &ring[(s * TILE_T + tl) * 256];
            *(float4*)(rb + bl * 4)       = make_float4(a0, a1, a2, a3);  // LSTM1 quad
            *(float4*)(rb + 128 + bl * 4) = make_float4(a4, a5, a6, a7);  // LSTM2 quad

            MBAR_ARRIVE(full_base + s * 8);   // release: orders this thread's STS

            if (k < NTILE - 1) {
                STS_TILE(1 - buf);
                asm volatile("bar.sync 1, %0;" :: "n"(PROD_T) : "memory");
                if (k < NTILE - 2) LDG_TILE(k + 2);
            }
        }
        #undef LDG_TILE
        #undef STS_TILE
    } else {
        // ================= CONSUMER =================
        const int ctid = tid - PROD_T;
        const int cw   = ctid >> 5;        // 0: LSTM1, 1: LSTM2
        const int lane = ctid & 31;        // batch

        const float* Whh = cw ? Whh2 : Whh1;
        const float whi = Whh[0] * 0.5f;
        const float whf = Whh[1] * 0.5f;
        const float whg = Whh[2];
        const float who = Whh[3] * 0.5f;

        float h = 0.0f, c = 0.0f;

        for (int ch = 0; ch < NTILE; ch++) {
            const int s = ch & (SLOTS - 1);
            mbar_wait_parity(full_base + s * 8, (ch >> 2) & 1);

            const float4* zp = (const float4*)&ring[(s * TILE_T) * 256 + cw * 128 + lane * 4];
            float4 z = zp[0];
            #pragma unroll
            for (int d = 0; d < TILE_T; d++) {
                float4 zn = z;
                if (d + 1 < TILE_T) zn = zp[(d + 1) * 64];  // prefetch next step

                float zi = fmaf(whi, h, z.x);
                float zf = fmaf(whf, h, z.y);
                float zg = fmaf(whg, h, z.z);
                float zo = fmaf(who, h, z.w);

                float gi = fmaf(0.5f, tanha(zi), 0.5f);  // sigmoid
                float gf = fmaf(0.5f, tanha(zf), 0.5f);
                float gg = tanha(zg);
                float go = fmaf(0.5f, tanha(zo), 0.5f);

                c = fmaf(gf, c, gi * gg);
                h = go * tanha(c);
                z = zn;
            }
            MBAR_ARRIVE(empty_base + s * 8);
        }

        if (cw == 1) h2s[lane] = h;
        asm volatile("bar.sync 2, %0;" :: "n"(CONS_T) : "memory");
        if (cw == 0) {
            float h2 = h2s[lane];
            float y = fmaf(Wout[0], h, fmaf(Wout[1], h2, bout[0]));
            out[bg * 32 + lane] = 1.0f / (1.0f + __expf(-y));
        }
    }
}

// ---------------------------------------------------------------------------
extern "C" void kernel_launch(void* const* d_in, const int* in_sizes, int n_in,
                              void* d_out, int out_size)
{
    const float* x    = (const float*)d_in[0];
    const float* Wih1 = (const float*)d_in[1];
    const float* Whh1 = (const float*)d_in[2];
    const float* b1   = (const float*)d_in[3];
    const float* Wih2 = (const float*)d_in[4];
    const float* Whh2 = (const float*)d_in[5];
    const float* b2   = (const float*)d_in[6];
    const float* Wout = (const float*)d_in[7];
    const float* bout = (const float*)d_in[8];

    cudaFuncSetAttribute(fused_kernel, cudaFuncAttributeMaxDynamicSharedMemorySize, SMEM_BYTES);
    fused_kernel<<<NGRP, NTHREADS, SMEM_BYTES>>>(
        x, Wih1, Whh1, b1, Wih2, Whh2, b2, Wout, bout, (float*)d_out);
}

// round 3
// speedup vs baseline: 2.1235x; 1.8130x over previous
#include <cuda_runtime.h>
#include <cstdint>

#define NGRP    128
#define T_TOT   512
#define TILE_T  16
#define NTILE   32
#define SLOTS   4
#define PROD_T  512
#define CONS_T  64
#define NTHREADS 576

#define XROW4       104                       // float4 per xbuf row (400 floats + pad; mult of 8 granules)
#define RING_FLOATS (SLOTS * TILE_T * 256)    // 16384 floats = 64 KB
#define XBUF_F4     (2 * 32 * XROW4)          // 6656 float4 = 104 KB
#define SMEM_BYTES  (RING_FLOATS * 4 + XBUF_F4 * 16)

__device__ __forceinline__ float tanha(float v) {
    float y;
    asm("tanh.approx.f32 %0, %1;" : "=f"(y) : "f"(v));
    return y;
}

__device__ __forceinline__ uint32_t smem_u32(const void* p) {
    uint32_t a;
    asm("{ .reg .u64 t; cvta.to.shared.u64 t, %1; cvt.u32.u64 %0, t; }" : "=r"(a) : "l"(p));
    return a;
}

#define MBAR_INIT(addr, cnt) \
    asm volatile("mbarrier.init.shared.b64 [%0], %1;" :: "r"(addr), "r"(cnt) : "memory")
#define MBAR_ARRIVE(addr) \
    asm volatile("mbarrier.arrive.release.cta.shared::cta.b64 _, [%0];" :: "r"(addr) : "memory")

__device__ __forceinline__ void mbar_wait_parity(uint32_t mbar, uint32_t parity) {
    uint32_t done;
    asm volatile(
        "{\n\t.reg .pred p;\n\t"
        "mbarrier.try_wait.parity.acquire.cta.shared::cta.b64 p, [%1], %2;\n\t"
        "selp.b32 %0, 1, 0, p;\n\t}"
        : "=r"(done) : "r"(mbar), "r"(parity) : "memory");
    if (!done) {
        asm volatile(
            "{\n\t.reg .pred P1;\n\t"
            "W_%=:\n\t"
            "mbarrier.try_wait.parity.acquire.cta.shared::cta.b64 P1, [%0], %1, 0x989680;\n\t"
            "@P1 bra.uni D_%=;\n\t"
            "bra.uni W_%=;\n\t"
            "D_%=:\n\t}"
            :: "r"(mbar), "r"(parity) : "memory");
    }
}

// ---------------------------------------------------------------------------
// Gate warps: lane = batch, thread handles 4 consecutive timesteps of one LSTM.
// NF = 12 (LSTM1, feature offset 0) or 13 (LSTM2, offset 12).
// ---------------------------------------------------------------------------
template <int NF>
__device__ __forceinline__ void gate_loop(
    const float4* __restrict__ xb4, float* __restrict__ ring,
    uint32_t full_base, uint32_t empty_base,
    int l, int tq, const float* __restrict__ Wih, const float* __restrict__ bp)
{
    constexpr int FOFF = (NF == 13) ? 12 : 0;
    constexpr int LOFF = (NF == 13) ? 128 : 0;

    float w[4][13], bb[4];
    #pragma unroll
    for (int g = 0; g < 4; g++) {
        float sc = (g == 2) ? 1.0f : 0.5f;
        bb[g] = bp[g] * sc;
        #pragma unroll
        for (int f = 0; f < NF; f++) w[g][f] = Wih[g * NF + f] * sc;
    }

    const int xl  = l & 7;
    const int tq4 = tq * 4;

    asm volatile("bar.sync 1, %0;" :: "n"(PROD_T) : "memory");  // prologue stage done

    for (int k = 0; k < NTILE; k++) {
        const int s = k & (SLOTS - 1);
        mbar_wait_parity(empty_base + s * 8, 1u ^ ((k >> 2) & 1));

        const float4* xr = xb4 + ((size_t)((k & 1) * 32 + l)) * XROW4;

        #pragma unroll
        for (int i = 0; i < 4; i++) {
            const int tloc = tq4 + i;
            const int q0 = (tloc * 25 + FOFF) >> 2;   // aligned window start; offset == i
            constexpr int NQMAX = 4;
            const int nq = (i + NF + 3) >> 2;         // folds per unrolled i

            float xa[16];
            #pragma unroll
            for (int j = 0; j < NQMAX; j++) {
                if (j < nq) {
                    float4 t = xr[(q0 + j) ^ xl];
                    xa[4 * j + 0] = t.x; xa[4 * j + 1] = t.y;
                    xa[4 * j + 2] = t.z; xa[4 * j + 3] = t.w;
                }
            }

            float a0 = bb[0], a1 = bb[1], a2 = bb[2], a3 = bb[3];
            #pragma unroll
            for (int f = 0; f < NF; f++) {
                float v = xa[i + f];
                a0 = fmaf(w[0][f], v, a0);
                a1 = fmaf(w[1][f], v, a1);
                a2 = fmaf(w[2][f], v, a2);
                a3 = fmaf(w[3][f], v, a3);
            }

            *(float4*)(ring + (size_t)(s * TILE_T + tloc) * 256 + LOFF + l * 4) =
                make_float4(a0, a1, a2, a3);
        }

        MBAR_ARRIVE(full_base + s * 8);
        asm volatile("bar.sync 1, %0;" :: "n"(PROD_T) : "memory");
    }
}

// ---------------------------------------------------------------------------
__global__ __launch_bounds__(NTHREADS, 1) void fused_kernel(
    const float* __restrict__ x,
    const float* __restrict__ Wih1, const float* __restrict__ Whh1, const float* __restrict__ b1,
    const float* __restrict__ Wih2, const float* __restrict__ Whh2, const float* __restrict__ b2,
    const float* __restrict__ Wout, const float* __restrict__ bout,
    float* __restrict__ out)
{
    extern __shared__ float smem[];
    float*  ring = smem;                              // [SLOTS][TILE_T][256]
    float4* xb4  = (float4*)(smem + RING_FLOATS);     // [2][32][XROW4]

    __shared__ __align__(8) uint64_t bars[2 * SLOTS];
    __shared__ float h2s[32];

    const int tid = threadIdx.x;
    const int wid = tid >> 5;
    const int bg  = blockIdx.x;

    const uint32_t full_base  = smem_u32(bars);
    const uint32_t empty_base = full_base + SLOTS * 8;

    if (tid == 0) {
        #pragma unroll
        for (int s = 0; s < SLOTS; s++) {
            MBAR_INIT(full_base  + s * 8, 256);   // gate threads arrive
            MBAR_INIT(empty_base + s * 8, CONS_T);
        }
    }
    __syncthreads();

    if (wid < 8) {
        // ================= STAGE WARPS (float4 LDG -> swizzled float4 STS) =====
        const int sj = tid;                            // 0..255
        const float4* xg = (const float4*)x;
        const size_t rowbase = (size_t)bg * 32 * 3200; // float4 per batch row = 3200

        #define STAGE(KK) do {                                                    \
            float4 r[13];                                                         \
            _Pragma("unroll")                                                     \
            for (int m = 0; m < 13; m++) {                                        \
                int i = m * 256 + sj;                                             \
                if (m < 12 || sj < 128) {                                         \
                    int b = i / 100, q = i - b * 100;                             \
                    r[m] = xg[rowbase + (size_t)b * 3200 + (KK) * 100 + q];       \
                }                                                                 \
            }                                                                     \
            float4* dst = xb4 + (size_t)(((KK) & 1) * 32) * XROW4;                \
            _Pragma("unroll")                                                     \
            for (int m = 0; m < 13; m++) {                                        \
                int i = m * 256 + sj;                                             \
                if (m < 12 || sj < 128) {                                         \
                    int b = i / 100, q = i - b * 100;                             \
                    dst[(size_t)b * XROW4 + (q ^ (b & 7))] = r[m];                \
                }                                                                 \
            }                                                                     \
        } while (0)

        STAGE(0);
        asm volatile("bar.sync 1, %0;" :: "n"(PROD_T) : "memory");
        for (int k = 0; k < NTILE; k++) {
            if (k + 1 < NTILE) STAGE(k + 1);
            asm volatile("bar.sync 1, %0;" :: "n"(PROD_T) : "memory");
        }
        #undef STAGE
    } else if (wid < 16) {
        // ================= GATE WARPS ==========================================
        const int gw = wid - 8;
        const int L  = gw & 1;        // 0: LSTM1, 1: LSTM2
        const int tq = gw >> 1;       // t-quad 0..3
        const int l  = tid & 31;      // batch lane
        if (L == 0) gate_loop<12>(xb4, ring, full_base, empty_base, l, tq, Wih1, b1);
        else        gate_loop<13>(xb4, ring, full_base, empty_base, l, tq, Wih2, b2);
    } else {
        // ================= CONSUMER (serial recurrence) ========================
        const int ctid = tid - PROD_T;
        const int cw   = ctid >> 5;   // 0: LSTM1, 1: LSTM2
        const int lane = ctid & 31;

        const float* Whh = cw ? Whh2 : Whh1;
        const float whi = Whh[0] * 0.5f;
        const float whf = Whh[1] * 0.5f;
        const float whg = Whh[2];
        const float who = Whh[3] * 0.5f;

        float h = 0.0f, c = 0.0f;

        for (int ch = 0; ch < NTILE; ch++) {
            const int s = ch & (SLOTS - 1);
            mbar_wait_parity(full_base + s * 8, (ch >> 2) & 1);

            const float4* zp = (const float4*)&ring[(size_t)(s * TILE_T) * 256 + cw * 128 + lane * 4];
            float4 z = zp[0];
            #pragma unroll
            for (int d = 0; d < TILE_T; d++) {
                float4 zn = z;
                if (d + 1 < TILE_T) zn = zp[(d + 1) * 64];

                float zi = fmaf(whi, h, z.x);
                float zf = fmaf(whf, h, z.y);
                float zg = fmaf(whg, h, z.z);
                float zo = fmaf(who, h, z.w);

                float gi = fmaf(0.5f, tanha(zi), 0.5f);
                float gf = fmaf(0.5f, tanha(zf), 0.5f);
                float gg = tanha(zg);
                float go = fmaf(0.5f, tanha(zo), 0.5f);

                c = fmaf(gf, c, gi * gg);
                h = go * tanha(c);
                z = zn;
            }
            MBAR_ARRIVE(empty_base + s * 8);
        }

        if (cw == 1) h2s[lane] = h;
        asm volatile("bar.sync 2, %0;" :: "n"(CONS_T) : "memory");
        if (cw == 0) {
            float h2 = h2s[lane];
            float y = fmaf(Wout[0], h, fmaf(Wout[1], h2, bout[0]));
            out[bg * 32 + lane] = 1.0f / (1.0f + __expf(-y));
        }
    }
}

// ---------------------------------------------------------------------------
extern "C" void kernel_launch(void* const* d_in, const int* in_sizes, int n_in,
                              void* d_out, int out_size)
{
    const float* x    = (const float*)d_in[0];
    const float* Wih1 = (const float*)d_in[1];
    const float* Whh1 = (const float*)d_in[2];
    const float* b1   = (const float*)d_in[3];
    const float* Wih2 = (const float*)d_in[4];
    const float* Whh2 = (const float*)d_in[5];
    const float* b2   = (const float*)d_in[6];
    const float* Wout = (const float*)d_in[7];
    const float* bout = (const float*)d_in[8];

    cudaFuncSetAttribute(fused_kernel, cudaFuncAttributeMaxDynamicSharedMemorySize, SMEM_BYTES);
    fused_kernel<<<NGRP, NTHREADS, SMEM_BYTES>>>(
        x, Wih1, Whh1, b1, Wih2, Whh2, b2, Wout, bout, (float*)d_out);
}